// round 12
// baseline (speedup 1.0000x reference)
#include <cuda_runtime.h>
#include <cuda_bf16.h>
#include <cstdint>

#define BB 24
#define DD 128
#define NN 2048
#define MM 2048
#define NM ((size_t)NN*(size_t)MM)

__device__ float g_S[(size_t)BB*NN*MM];
__device__ float g_sq[BB*MM], g_sc[BB*NN], g_rmax[BB*NN], g_cmax[BB*MM];
__device__ __nv_bfloat16 g_At[2][BB][NN][DD];
__device__ __nv_bfloat16 g_Qt[2][BB][MM][DD];
__device__ __nv_bfloat16 g_Cs[2][BB][DD][NN];
__device__ __nv_bfloat16 g_Qs[2][BB][DD][MM];
__device__ __nv_bfloat16 g_Vs[2][BB][DD][MM];

// ---- threefry2x32 (JAX partitionable, key (0,42)) ----
__device__ __forceinline__ unsigned rotl(unsigned x,int d){ return __funnelshift_l(x,x,d); }
#define TFR(a,b,c,d,ka,kb) \
  x0+=x1; x1=rotl(x1,(a))^x0; x0+=x1; x1=rotl(x1,(b))^x0; \
  x0+=x1; x1=rotl(x1,(c))^x0; x0+=x1; x1=rotl(x1,(d))^x0; \
  x0+=(ka); x1+=(kb);
__device__ __forceinline__ unsigned tf_bits(unsigned ctr){
  const unsigned K0=0u,K1=42u,K2=0x1BD11BDAu^K0^K1;
  unsigned x0=K0,x1=ctr+K1;
  TFR(13,15,26,6,K1,K2+1u) TFR(17,29,16,24,K2,K0+2u) TFR(13,15,26,6,K0,K1+3u)
  TFR(17,29,16,24,K1,K2+4u) TFR(13,15,26,6,K2,K0+5u)
  return x0^x1;
}
__device__ __forceinline__ float dropf(float v,unsigned i){
  unsigned b=tf_bits(i);
  float u=__uint_as_float((b>>9)|0x3f800000u)-1.0f;
  return u<0.9f ? v*(1.0f/0.9f) : 0.0f;
}
__device__ __forceinline__ void atomicMaxF(float* a,float v){
  if(v>=0.0f) atomicMax((int*)a,__float_as_int(v));
  else        atomicMin((unsigned*)a,__float_as_uint(v));
}

// ---- warp MMA helpers ----
__device__ __forceinline__ uint32_t smem_u32(const void* p){
  uint32_t a;
  asm("{ .reg .u64 t; cvta.to.shared.u64 t, %1; cvt.u32.u64 %0, t; }":"=r"(a):"l"(p));
  return a;
}
__device__ __forceinline__ void ldm4(uint32_t* f, uint32_t a){
  asm volatile("ldmatrix.sync.aligned.m8n8.x4.shared.b16 {%0,%1,%2,%3}, [%4];"
    :"=r"(f[0]),"=r"(f[1]),"=r"(f[2]),"=r"(f[3]):"r"(a));
}
__device__ __forceinline__ void mma16816(float* d, const uint32_t* a, const uint32_t* b){
  asm volatile("mma.sync.aligned.m16n8k16.row.col.f32.bf16.bf16.f32 "
    "{%0,%1,%2,%3},{%4,%5,%6,%7},{%8,%9},{%0,%1,%2,%3};"
    : "+f"(d[0]),"+f"(d[1]),"+f"(d[2]),"+f"(d[3])
    : "r"(a[0]),"r"(a[1]),"r"(a[2]),"r"(a[3]),"r"(b[0]),"r"(b[1]));
}
// warp computes 64(M)x32(N); 3-pass bf16 split: hi*hi + lo*hi + hi*lo.
__device__ __forceinline__ void mma_block(
  float acc[4][4][4], uint32_t Ah, uint32_t Al, uint32_t Bh, uint32_t Bl,
  int stride, int Kc, int lane)
{
  int lr=lane&15, lc=lane>>4;
#pragma unroll 1
  for(int k0=0;k0<Kc;k0+=16){
    uint32_t bh[2][4], bl[2][4];
#pragma unroll
    for(int mp=0;mp<2;mp++){
      uint32_t ro=(uint32_t)((mp*16+lr)*stride + k0 + lc*8)*2;
      ldm4(bh[mp], Bh+ro);
      ldm4(bl[mp], Bl+ro);
    }
#pragma unroll
    for(int i=0;i<4;i++){
      uint32_t ro=(uint32_t)((i*16+lr)*stride + k0 + lc*8)*2;
      uint32_t ah[4], al[4];
      ldm4(ah, Ah+ro); ldm4(al, Al+ro);
#pragma unroll
      for(int j=0;j<4;j++){
        int mp=j>>1, s=j&1;
        uint32_t bp[2]={bh[mp][s], bh[mp][s+2]};
        uint32_t bq[2]={bl[mp][s], bl[mp][s+2]};
        mma16816(acc[i][j], ah, bp);
        mma16816(acc[i][j], al, bp);
        mma16816(acc[i][j], ah, bq);
      }
    }
  }
}
// cheap truncation split: hi = top-16-bit truncation (exact bf16), lo = rounded remainder
__device__ __forceinline__ void splitpack_t(float e0,float e1,uint32_t&hp,uint32_t&lp){
  uint32_t u0=__float_as_uint(e0), u1=__float_as_uint(e1);
  hp=__byte_perm(u0,u1,0x7632);
  float l0=e0-__uint_as_float(u0&0xFFFF0000u);
  float l1=e1-__uint_as_float(u1&0xFFFF0000u);
  asm("cvt.rn.bf16x2.f32 %0, %1, %2;":"=r"(lp):"f"(l1),"f"(l0));
}

// ---- prep kernels (proven) ----
__global__ void k_init(){
  int i=blockIdx.x*256+threadIdx.x;
  if(i<BB*NN){ float nf=__int_as_float(0xff800000); g_rmax[i]=nf; g_cmax[i]=nf; }
}
__global__ void k_sqsc(const float* __restrict__ Q_,const float* __restrict__ C_,
                       const float* __restrict__ W_){
  int b=blockIdx.y, m=blockIdx.x*256+threadIdx.x;
  const float* wb=W_+b*384;
  const float* Qb=Q_+(size_t)b*DD*MM;
  const float* Cb=C_+(size_t)b*DD*NN;
  float aq=0.f,ac=0.f;
#pragma unroll 4
  for(int d=0;d<DD;d++){
    aq=fmaf(wb[d],Qb[(size_t)d*MM+m],aq);
    ac=fmaf(wb[128+d],Cb[(size_t)d*NN+m],ac);
  }
  g_sq[b*MM+m]=aq; g_sc[b*NN+m]=ac;
}
__global__ void k_split(const float* __restrict__ C_,const float* __restrict__ Q_){
  const size_t HALF=(size_t)BB*DD*NN/4;
  size_t i=(size_t)blockIdx.x*256+threadIdx.x;
  int wq=i>=HALF; size_t j=wq?i-HALF:i;
  float4 x=(wq?(const float4*)Q_:(const float4*)C_)[j];
  float e[4]={x.x,x.y,x.z,x.w};
  __align__(8) __nv_bfloat16 hh[4],ll[4];
#pragma unroll
  for(int k=0;k<4;k++){ hh[k]=__float2bfloat16(e[k]); ll[k]=__float2bfloat16(e[k]-__bfloat162float(hh[k])); }
  uint2* dh=wq?(uint2*)&g_Qs[0][0][0][0]:(uint2*)&g_Cs[0][0][0][0];
  uint2* dl=wq?(uint2*)&g_Qs[1][0][0][0]:(uint2*)&g_Cs[1][0][0][0];
  dh[j]=*(uint2*)hh; dl[j]=*(uint2*)ll;
}
__global__ void __launch_bounds__(256) k_tr(const float* __restrict__ C_,
                                            const float* __restrict__ Q_,
                                            const float* __restrict__ W_){
  __shared__ float T[32][33]; __shared__ float w_s[32];
  int b=blockIdx.z%BB, wq=blockIdx.z/BB;
  int n0=blockIdx.x*32, d0=blockIdx.y*32, tid=threadIdx.x;
  const float* src=wq?Q_:C_;
  if(tid<32) w_s[tid]=wq?1.0f:W_[b*384+256+d0+tid];
  __syncthreads();
  int dl=tid>>5, c=tid&31;
#pragma unroll
  for(int i=0;i<4;i++){
    int d=dl+i*8;
    T[d][c]=src[((size_t)b*DD+d0+d)*NN+n0+c]*w_s[d];
  }
  __syncthreads();
  int nl=tid>>3, q=tid&7;
  float e[4];
#pragma unroll
  for(int k=0;k<4;k++) e[k]=T[q*4+k][nl];
  __align__(8) __nv_bfloat16 hh[4],ll[4];
#pragma unroll
  for(int k=0;k<4;k++){ hh[k]=__float2bfloat16(e[k]); ll[k]=__float2bfloat16(e[k]-__bfloat162float(hh[k])); }
  __nv_bfloat16* ph=wq?&g_Qt[0][b][n0+nl][d0+q*4]:&g_At[0][b][n0+nl][d0+q*4];
  __nv_bfloat16* pl=wq?&g_Qt[1][b][n0+nl][d0+q*4]:&g_At[1][b][n0+nl][d0+q*4];
  *(uint2*)ph=*(uint2*)hh; *(uint2*)pl=*(uint2*)ll;
}

// ---- S GEMM (HMMA) + fused row/col maxes (proven round-10) ----
#define PK 136
__global__ void __launch_bounds__(256) k_gemmS(){
  extern __shared__ char smc[];
  __shared__ float sq_s[128], sc_s[128];
  uint32_t sb=smem_u32(smc);
  const uint32_t oAh=0u,oAl=34816u,oBh=69632u,oBl=104448u;
  int b=blockIdx.z, n0=blockIdx.y*128, m0=blockIdx.x*128, tid=threadIdx.x;
  if(tid<128){ sq_s[tid]=g_sq[b*MM+m0+tid]; sc_s[tid]=g_sc[b*NN+n0+tid]; }
  {
    int r=tid>>1, sg=(tid&1)*8;
    const uint4* a0=(const uint4*)&g_At[0][b][n0+r][0];
    const uint4* a1=(const uint4*)&g_At[1][b][n0+r][0];
    const uint4* b0=(const uint4*)&g_Qt[0][b][m0+r][0];
    const uint4* b1=(const uint4*)&g_Qt[1][b][m0+r][0];
#pragma unroll
    for(int j=0;j<8;j++){
      int ci=sg+j;
      uint32_t off=(uint32_t)(r*PK+ci*8)*2;
      *(uint4*)(smc+oAh+off)=a0[ci];
      *(uint4*)(smc+oAl+off)=a1[ci];
      *(uint4*)(smc+oBh+off)=b0[ci];
      *(uint4*)(smc+oBl+off)=b1[ci];
    }
  }
  __syncthreads();
  int wid=tid>>5, lane=tid&31, wn=wid>>2, wm=wid&3;
  float acc[4][4][4]={};
  mma_block(acc, sb+oAh+(uint32_t)(wn*64*PK)*2, sb+oAl+(uint32_t)(wn*64*PK)*2,
                 sb+oBh+(uint32_t)(wm*32*PK)*2, sb+oBl+(uint32_t)(wm*32*PK)*2,
            PK, 128, lane);
  __syncthreads();
  float* stg=(float*)smc;
  int gr=lane>>2, tg=lane&3;
#pragma unroll
  for(int i=0;i<4;i++)
#pragma unroll
    for(int j=0;j<4;j++){
      int nl=wn*64+i*16+gr, ml=wm*32+j*8+tg*2;
      stg[nl*132+ml]      =acc[i][j][0]+sc_s[nl]+sq_s[ml];
      stg[nl*132+ml+1]    =acc[i][j][1]+sc_s[nl]+sq_s[ml+1];
      stg[(nl+8)*132+ml]  =acc[i][j][2]+sc_s[nl+8]+sq_s[ml];
      stg[(nl+8)*132+ml+1]=acc[i][j][3]+sc_s[nl+8]+sq_s[ml+1];
    }
  __syncthreads();
  {
    int nl=tid>>1, mh=(tid&1)*64;
    float mx=__int_as_float(0xff800000);
    float* Sg=g_S+(size_t)b*NM+(size_t)(n0+nl)*MM+m0+mh;
#pragma unroll
    for(int q=0;q<16;q++){
      float4 v=*(float4*)&stg[nl*132+mh+q*4];
      mx=fmaxf(mx,fmaxf(fmaxf(v.x,v.y),fmaxf(v.z,v.w)));
      *(float4*)&Sg[q*4]=v;
    }
    atomicMaxF(&g_rmax[b*NN+n0+nl],mx);
    int ml=tid>>1, nh=(tid&1)*64;
    float cx=__int_as_float(0xff800000);
#pragma unroll 8
    for(int r2=0;r2<64;r2++) cx=fmaxf(cx,stg[(nh+r2)*132+ml]);
    atomicMaxF(&g_cmax[b*MM+m0+ml],cx);
  }
}

// ---- V GEMM (round-10 base) + folded csum ----
__global__ void __launch_bounds__(256) k_gemmV(){
  extern __shared__ char smc[];
  __shared__ float cmx[128], csp[128][2], cin[128];
  uint32_t sb=smem_u32(smc);
  const uint32_t oAh=0u,oAl=18432u,oBh=36864u,oBl=55296u,oSs=73728u;
  float* Sst=(float*)(smc+oSs);
  int b=blockIdx.y, m0=blockIdx.x*128, tid=threadIdx.x;
  if(tid<128) cmx[tid]=g_cmax[b*MM+m0+tid];
  __syncthreads();
  int wid=tid>>5, lane=tid&31, wn=wid>>2, wm=wid&3;
  int me=tid>>1, nhb=tid&1, nh=nhb*32;
  float cme=cmx[me], csum=0.f;
  float acc[4][4][4]={};
  for(int c=0;c<32;c++){
    int n0c=c*64;
    __syncthreads();
    {
      int d=tid>>1, sg=(tid&1)*4;
      const uint4* ph=(const uint4*)&g_Cs[0][b][d][n0c];
      const uint4* pl=(const uint4*)&g_Cs[1][b][d][n0c];
#pragma unroll
      for(int j=0;j<4;j++){
        uint32_t off=(uint32_t)(d*72+(sg+j)*8)*2;
        *(uint4*)(smc+oAh+off)=ph[sg+j];
        *(uint4*)(smc+oAl+off)=pl[sg+j];
      }
      int n=tid>>2, q=tid&3;
      const float4* sr=(const float4*)(g_S+(size_t)b*NM+(size_t)(n0c+n)*MM+m0);
#pragma unroll
      for(int j=0;j<8;j++) *(float4*)&Sst[n*132+(q*8+j)*4]=sr[q*8+j];
    }
    __syncthreads();
#pragma unroll
    for(int np=0;np<16;np++){
      int n=nh+np*2;
      float e0=__expf(Sst[n*132+me]-cme);
      float e1=__expf(Sst[(n+1)*132+me]-cme);
      csum+=e0+e1;
      uint32_t hp,lp; splitpack_t(e0,e1,hp,lp);
      uint32_t off=(uint32_t)(me*72+n)*2;
      *(uint32_t*)(smc+oBh+off)=hp;
      *(uint32_t*)(smc+oBl+off)=lp;
    }
    __syncthreads();
    mma_block(acc, sb+oAh+(uint32_t)(wn*64*72)*2, sb+oAl+(uint32_t)(wn*64*72)*2,
                   sb+oBh+(uint32_t)(wm*32*72)*2, sb+oBl+(uint32_t)(wm*32*72)*2,
              72, 64, lane);
  }
  csp[me][nhb]=csum;
  __syncthreads();
  if(tid<128) cin[tid]=1.0f/(csp[tid][0]+csp[tid][1]);
  __syncthreads();
  float* stg=(float*)smc;
  int gr=lane>>2, tg=lane&3;
#pragma unroll
  for(int i=0;i<4;i++)
#pragma unroll
    for(int j=0;j<4;j++){
      int dl2=wn*64+i*16+gr, ml=wm*32+j*8+tg*2;
      stg[dl2*132+ml]      =acc[i][j][0]*cin[ml];
      stg[dl2*132+ml+1]    =acc[i][j][1]*cin[ml+1];
      stg[(dl2+8)*132+ml]  =acc[i][j][2]*cin[ml];
      stg[(dl2+8)*132+ml+1]=acc[i][j][3]*cin[ml+1];
    }
  __syncthreads();
  {
    int d=tid>>1, mhs=(tid&1)*64;
    __nv_bfloat16* vh=&g_Vs[0][b][d][m0+mhs];
    __nv_bfloat16* vl=&g_Vs[1][b][d][m0+mhs];
#pragma unroll
    for(int q=0;q<8;q++){
      __align__(16) __nv_bfloat16 hh[8],ll[8];
#pragma unroll
      for(int e=0;e<8;e++){
        float f=stg[d*132+mhs+q*8+e];
        hh[e]=__float2bfloat16(f);
        ll[e]=__float2bfloat16(f-__bfloat162float(hh[e]));
      }
      *(uint4*)&vh[q*8]=*(uint4*)hh;
      *(uint4*)&vl[q*8]=*(uint4*)ll;
    }
  }
}

// ---- merged A/Bt GEMM: 256(P)x64(n) tile, acc=64 regs, single E pass, folded rsum ----
__global__ void __launch_bounds__(256) k_gemmABt(const float* __restrict__ C_,
                                                 float* __restrict__ out){
  extern __shared__ char smc[];
  __shared__ float rmx[64], rsp[64][4], rin[64];
  uint32_t sb=smem_u32(smc);
  const uint32_t oPh=0u,oPl=36864u,oEh=73728u,oEl=82944u;
  int b=blockIdx.y, n0=blockIdx.x*64, tid=threadIdx.x;
  if(tid<64) rmx[tid]=g_rmax[b*NN+n0+tid];
  __syncthreads();
  int wid=tid>>5, lane=tid&31, wd=wid&3, wnc=wid>>2;
  int ne=tid>>2, seg=(tid&3)*16;
  float rme=rmx[ne], rsum=0.f;
  const __nv_bfloat16* Q0=&g_Qs[0][b][0][0];
  const __nv_bfloat16* Q1=&g_Qs[1][b][0][0];
  const __nv_bfloat16* V0=&g_Vs[0][b][0][0];
  const __nv_bfloat16* V1=&g_Vs[1][b][0][0];
  float acc[4][4][4]={};
  for(int c=0;c<32;c++){
    int m0c=c*64;
    __syncthreads();
    {
      int r=tid;
      const uint4* ph=(r<128)?(const uint4*)(Q0+(size_t)r*MM+m0c):(const uint4*)(V0+(size_t)(r-128)*MM+m0c);
      const uint4* pl=(r<128)?(const uint4*)(Q1+(size_t)r*MM+m0c):(const uint4*)(V1+(size_t)(r-128)*MM+m0c);
#pragma unroll
      for(int j=0;j<8;j++){
        uint32_t off=(uint32_t)(r*72+j*8)*2;
        *(uint4*)(smc+oPh+off)=ph[j];
        *(uint4*)(smc+oPl+off)=pl[j];
      }
    }
    {
      const float4* sr=(const float4*)(g_S+(size_t)b*NM+(size_t)(n0+ne)*MM+m0c+seg);
#pragma unroll
      for(int j=0;j<4;j++){
        float4 v=sr[j];
        float e0=__expf(v.x-rme), e1=__expf(v.y-rme);
        float e2=__expf(v.z-rme), e3=__expf(v.w-rme);
        rsum+=(e0+e1)+(e2+e3);
        uint32_t h0,l0,h1,l1;
        splitpack_t(e0,e1,h0,l0); splitpack_t(e2,e3,h1,l1);
        uint32_t off=(uint32_t)(ne*72+seg+j*4)*2;
        *(uint2*)(smc+oEh+off)=make_uint2(h0,h1);
        *(uint2*)(smc+oEl+off)=make_uint2(l0,l1);
      }
    }
    __syncthreads();
    mma_block(acc, sb+oPh+(uint32_t)(wd*64*72)*2, sb+oPl+(uint32_t)(wd*64*72)*2,
                   sb+oEh+(uint32_t)(wnc*32*72)*2, sb+oEl+(uint32_t)(wnc*32*72)*2,
              72, 64, lane);
  }
  rsp[ne][tid&3]=rsum;
  __syncthreads();
  if(tid<64) rin[tid]=1.0f/((rsp[tid][0]+rsp[tid][1])+(rsp[tid][2]+rsp[tid][3]));
  __syncthreads();
  float* stg=(float*)smc;  // 256x68 floats = 69632B <= 92160B
  int gr=lane>>2, tg=lane&3;
#pragma unroll
  for(int i=0;i<4;i++)
#pragma unroll
    for(int j=0;j<4;j++){
      int gl=wd*64+i*16+gr, nl=wnc*32+j*8+tg*2;
      stg[gl*68+nl]      =acc[i][j][0]*rin[nl];
      stg[gl*68+nl+1]    =acc[i][j][1]*rin[nl+1];
      stg[(gl+8)*68+nl]  =acc[i][j][2]*rin[nl];
      stg[(gl+8)*68+nl+1]=acc[i][j][3]*rin[nl+1];
    }
  __syncthreads();
  {
    int nq=tid&15, dg=tid>>4;
    unsigned ng=n0+nq*4;
#pragma unroll
    for(int dd=0;dd<8;dd++){
      int d=dg*8+dd;
      float4 a4=*(float4*)&stg[d*68+nq*4];
      float4 t4=*(float4*)&stg[(128+d)*68+nq*4];
      float4 c4=*(const float4*)&C_[((size_t)b*DD+d)*NN+ng];
      unsigned i0=(unsigned)(b*512+d)*2048u+ng;
      float4 o;
      o.x=dropf(c4.x,i0);   o.y=dropf(c4.y,i0+1);
      o.z=dropf(c4.z,i0+2); o.w=dropf(c4.w,i0+3);
      *(float4*)&out[(size_t)(b*512+d)*2048+ng]=o;
      unsigned i1=i0+128u*2048u;
      o.x=dropf(a4.x,i1);   o.y=dropf(a4.y,i1+1);
      o.z=dropf(a4.z,i1+2); o.w=dropf(a4.w,i1+3);
      *(float4*)&out[(size_t)(b*512+128+d)*2048+ng]=o;
      unsigned i2=i0+256u*2048u;
      o.x=dropf(c4.x*a4.x,i2);   o.y=dropf(c4.y*a4.y,i2+1);
      o.z=dropf(c4.z*a4.z,i2+2); o.w=dropf(c4.w*a4.w,i2+3);
      *(float4*)&out[(size_t)(b*512+256+d)*2048+ng]=o;
      unsigned i3=i0+384u*2048u;
      o.x=dropf(c4.x*t4.x,i3);   o.y=dropf(c4.y*t4.y,i3+1);
      o.z=dropf(c4.z*t4.z,i3+2); o.w=dropf(c4.w*t4.w,i3+3);
      *(float4*)&out[(size_t)(b*512+384+d)*2048+ng]=o;
    }
  }
}

extern "C" void kernel_launch(void* const* d_in, const int* in_sizes, int n_in,
                              void* d_out, int out_size){
  const float* C_=(const float*)d_in[0];
  const float* Q_=(const float*)d_in[1];
  const float* W_=(const float*)d_in[2];
  float* out=(float*)d_out;
  cudaFuncSetAttribute(k_gemmS,  cudaFuncAttributeMaxDynamicSharedMemorySize, 139264);
  cudaFuncSetAttribute(k_gemmV,  cudaFuncAttributeMaxDynamicSharedMemorySize, 107520);
  cudaFuncSetAttribute(k_gemmABt,cudaFuncAttributeMaxDynamicSharedMemorySize, 92160);
  k_init <<<(BB*NN+255)/256,256>>>();
  k_sqsc <<<dim3(MM/256,BB),256>>>(Q_,C_,W_);
  k_split<<<(unsigned)((size_t)2*BB*DD*NN/4/256),256>>>(C_,Q_);
  k_tr   <<<dim3(NN/32,DD/32,BB*2),256>>>(C_,Q_,W_);
  k_gemmS<<<dim3(MM/128,NN/128,BB),256,139264>>>();
  k_gemmV<<<dim3(MM/128,BB),256,107520>>>();
  k_gemmABt<<<dim3(NN/64,BB),256,92160>>>(C_,out);
}

// round 14
// speedup vs baseline: 1.2977x; 1.2977x over previous
#include <cuda_runtime.h>
#include <cuda_bf16.h>
#include <cstdint>

#define BB 24
#define DD 128
#define NN 2048
#define MM 2048
#define NM ((size_t)NN*(size_t)MM)

__device__ float g_S[(size_t)BB*NN*MM];
__device__ float g_sq[BB*MM], g_sc[BB*NN], g_rmax[BB*NN], g_cmax[BB*MM];
__device__ __nv_bfloat16 g_At[2][BB][NN][DD];
__device__ __nv_bfloat16 g_Qt[2][BB][MM][DD];
__device__ __nv_bfloat16 g_Cs[2][BB][DD][NN];
__device__ __nv_bfloat16 g_Qs[2][BB][DD][MM];
__device__ __nv_bfloat16 g_Vs[2][BB][DD][MM];

// ---- threefry2x32 (JAX partitionable, key (0,42)) ----
__device__ __forceinline__ unsigned rotl(unsigned x,int d){ return __funnelshift_l(x,x,d); }
#define TFR(a,b,c,d,ka,kb) \
  x0+=x1; x1=rotl(x1,(a))^x0; x0+=x1; x1=rotl(x1,(b))^x0; \
  x0+=x1; x1=rotl(x1,(c))^x0; x0+=x1; x1=rotl(x1,(d))^x0; \
  x0+=(ka); x1+=(kb);
__device__ __forceinline__ unsigned tf_bits(unsigned ctr){
  const unsigned K0=0u,K1=42u,K2=0x1BD11BDAu^K0^K1;
  unsigned x0=K0,x1=ctr+K1;
  TFR(13,15,26,6,K1,K2+1u) TFR(17,29,16,24,K2,K0+2u) TFR(13,15,26,6,K0,K1+3u)
  TFR(17,29,16,24,K1,K2+4u) TFR(13,15,26,6,K2,K0+5u)
  return x0^x1;
}
__device__ __forceinline__ float dropf(float v,unsigned i){
  unsigned b=tf_bits(i);
  float u=__uint_as_float((b>>9)|0x3f800000u)-1.0f;
  return u<0.9f ? v*(1.0f/0.9f) : 0.0f;
}
__device__ __forceinline__ void atomicMaxF(float* a,float v){
  if(v>=0.0f) atomicMax((int*)a,__float_as_int(v));
  else        atomicMin((unsigned*)a,__float_as_uint(v));
}

// ---- warp MMA helpers ----
__device__ __forceinline__ uint32_t smem_u32(const void* p){
  uint32_t a;
  asm("{ .reg .u64 t; cvta.to.shared.u64 t, %1; cvt.u32.u64 %0, t; }":"=r"(a):"l"(p));
  return a;
}
__device__ __forceinline__ void ldm4(uint32_t* f, uint32_t a){
  asm volatile("ldmatrix.sync.aligned.m8n8.x4.shared.b16 {%0,%1,%2,%3}, [%4];"
    :"=r"(f[0]),"=r"(f[1]),"=r"(f[2]),"=r"(f[3]):"r"(a));
}
__device__ __forceinline__ void mma16816(float* d, const uint32_t* a, const uint32_t* b){
  asm volatile("mma.sync.aligned.m16n8k16.row.col.f32.bf16.bf16.f32 "
    "{%0,%1,%2,%3},{%4,%5,%6,%7},{%8,%9},{%0,%1,%2,%3};"
    : "+f"(d[0]),"+f"(d[1]),"+f"(d[2]),"+f"(d[3])
    : "r"(a[0]),"r"(a[1]),"r"(a[2]),"r"(a[3]),"r"(b[0]),"r"(b[1]));
}
// warp computes 64(M)x32(N); 3-pass bf16 split: hi*hi + lo*hi + hi*lo.
__device__ __forceinline__ void mma_block(
  float acc[4][4][4], uint32_t Ah, uint32_t Al, uint32_t Bh, uint32_t Bl,
  int stride, int Kc, int lane)
{
  int lr=lane&15, lc=lane>>4;
#pragma unroll 1
  for(int k0=0;k0<Kc;k0+=16){
    uint32_t bh[2][4], bl[2][4];
#pragma unroll
    for(int mp=0;mp<2;mp++){
      uint32_t ro=(uint32_t)((mp*16+lr)*stride + k0 + lc*8)*2;
      ldm4(bh[mp], Bh+ro);
      ldm4(bl[mp], Bl+ro);
    }
#pragma unroll
    for(int i=0;i<4;i++){
      uint32_t ro=(uint32_t)((i*16+lr)*stride + k0 + lc*8)*2;
      uint32_t ah[4], al[4];
      ldm4(ah, Ah+ro); ldm4(al, Al+ro);
#pragma unroll
      for(int j=0;j<4;j++){
        int mp=j>>1, s=j&1;
        uint32_t bp[2]={bh[mp][s], bh[mp][s+2]};
        uint32_t bq[2]={bl[mp][s], bl[mp][s+2]};
        mma16816(acc[i][j], ah, bp);
        mma16816(acc[i][j], al, bp);
        mma16816(acc[i][j], ah, bq);
      }
    }
  }
}
// truncation split: hi = top-16-bit truncation (exact bf16), lo = rounded remainder
__device__ __forceinline__ void splitpack_t(float e0,float e1,uint32_t&hp,uint32_t&lp){
  uint32_t u0=__float_as_uint(e0), u1=__float_as_uint(e1);
  hp=__byte_perm(u0,u1,0x7632);
  float l0=e0-__uint_as_float(u0&0xFFFF0000u);
  float l1=e1-__uint_as_float(u1&0xFFFF0000u);
  asm("cvt.rn.bf16x2.f32 %0, %1, %2;":"=r"(lp):"f"(l1),"f"(l0));
}

// ---- prep kernels (proven) ----
__global__ void k_init(){
  int i=blockIdx.x*256+threadIdx.x;
  if(i<BB*NN){ float nf=__int_as_float(0xff800000); g_rmax[i]=nf; g_cmax[i]=nf; }
}
__global__ void k_sqsc(const float* __restrict__ Q_,const float* __restrict__ C_,
                       const float* __restrict__ W_){
  int b=blockIdx.y, m=blockIdx.x*256+threadIdx.x;
  const float* wb=W_+b*384;
  const float* Qb=Q_+(size_t)b*DD*MM;
  const float* Cb=C_+(size_t)b*DD*NN;
  float aq=0.f,ac=0.f;
#pragma unroll 4
  for(int d=0;d<DD;d++){
    aq=fmaf(wb[d],Qb[(size_t)d*MM+m],aq);
    ac=fmaf(wb[128+d],Cb[(size_t)d*NN+m],ac);
  }
  g_sq[b*MM+m]=aq; g_sc[b*NN+m]=ac;
}
__global__ void k_split(const float* __restrict__ C_,const float* __restrict__ Q_){
  const size_t HALF=(size_t)BB*DD*NN/4;
  size_t i=(size_t)blockIdx.x*256+threadIdx.x;
  int wq=i>=HALF; size_t j=wq?i-HALF:i;
  float4 x=(wq?(const float4*)Q_:(const float4*)C_)[j];
  float e[4]={x.x,x.y,x.z,x.w};
  __align__(8) __nv_bfloat16 hh[4],ll[4];
#pragma unroll
  for(int k=0;k<4;k++){ hh[k]=__float2bfloat16(e[k]); ll[k]=__float2bfloat16(e[k]-__bfloat162float(hh[k])); }
  uint2* dh=wq?(uint2*)&g_Qs[0][0][0][0]:(uint2*)&g_Cs[0][0][0][0];
  uint2* dl=wq?(uint2*)&g_Qs[1][0][0][0]:(uint2*)&g_Cs[1][0][0][0];
  dh[j]=*(uint2*)hh; dl[j]=*(uint2*)ll;
}
__global__ void __launch_bounds__(256) k_tr(const float* __restrict__ C_,
                                            const float* __restrict__ Q_,
                                            const float* __restrict__ W_){
  __shared__ float T[32][33]; __shared__ float w_s[32];
  int b=blockIdx.z%BB, wq=blockIdx.z/BB;
  int n0=blockIdx.x*32, d0=blockIdx.y*32, tid=threadIdx.x;
  const float* src=wq?Q_:C_;
  if(tid<32) w_s[tid]=wq?1.0f:W_[b*384+256+d0+tid];
  __syncthreads();
  int dl=tid>>5, c=tid&31;
#pragma unroll
  for(int i=0;i<4;i++){
    int d=dl+i*8;
    T[d][c]=src[((size_t)b*DD+d0+d)*NN+n0+c]*w_s[d];
  }
  __syncthreads();
  int nl=tid>>3, q=tid&7;
  float e[4];
#pragma unroll
  for(int k=0;k<4;k++) e[k]=T[q*4+k][nl];
  __align__(8) __nv_bfloat16 hh[4],ll[4];
#pragma unroll
  for(int k=0;k<4;k++){ hh[k]=__float2bfloat16(e[k]); ll[k]=__float2bfloat16(e[k]-__bfloat162float(hh[k])); }
  __nv_bfloat16* ph=wq?&g_Qt[0][b][n0+nl][d0+q*4]:&g_At[0][b][n0+nl][d0+q*4];
  __nv_bfloat16* pl=wq?&g_Qt[1][b][n0+nl][d0+q*4]:&g_At[1][b][n0+nl][d0+q*4];
  *(uint2*)ph=*(uint2*)hh; *(uint2*)pl=*(uint2*)ll;
}

// ---- S GEMM (HMMA) + fused row/col maxes (proven round-10, unchanged) ----
#define PK 136
__global__ void __launch_bounds__(256) k_gemmS(){
  extern __shared__ char smc[];
  __shared__ float sq_s[128], sc_s[128];
  uint32_t sb=smem_u32(smc);
  const uint32_t oAh=0u,oAl=34816u,oBh=69632u,oBl=104448u;
  int b=blockIdx.z, n0=blockIdx.y*128, m0=blockIdx.x*128, tid=threadIdx.x;
  if(tid<128){ sq_s[tid]=g_sq[b*MM+m0+tid]; sc_s[tid]=g_sc[b*NN+n0+tid]; }
  {
    int r=tid>>1, sg=(tid&1)*8;
    const uint4* a0=(const uint4*)&g_At[0][b][n0+r][0];
    const uint4* a1=(const uint4*)&g_At[1][b][n0+r][0];
    const uint4* b0=(const uint4*)&g_Qt[0][b][m0+r][0];
    const uint4* b1=(const uint4*)&g_Qt[1][b][m0+r][0];
#pragma unroll
    for(int j=0;j<8;j++){
      int ci=sg+j;
      uint32_t off=(uint32_t)(r*PK+ci*8)*2;
      *(uint4*)(smc+oAh+off)=a0[ci];
      *(uint4*)(smc+oAl+off)=a1[ci];
      *(uint4*)(smc+oBh+off)=b0[ci];
      *(uint4*)(smc+oBl+off)=b1[ci];
    }
  }
  __syncthreads();
  int wid=tid>>5, lane=tid&31, wn=wid>>2, wm=wid&3;
  float acc[4][4][4]={};
  mma_block(acc, sb+oAh+(uint32_t)(wn*64*PK)*2, sb+oAl+(uint32_t)(wn*64*PK)*2,
                 sb+oBh+(uint32_t)(wm*32*PK)*2, sb+oBl+(uint32_t)(wm*32*PK)*2,
            PK, 128, lane);
  __syncthreads();
  float* stg=(float*)smc;
  int gr=lane>>2, tg=lane&3;
#pragma unroll
  for(int i=0;i<4;i++)
#pragma unroll
    for(int j=0;j<4;j++){
      int nl=wn*64+i*16+gr, ml=wm*32+j*8+tg*2;
      stg[nl*132+ml]      =acc[i][j][0]+sc_s[nl]+sq_s[ml];
      stg[nl*132+ml+1]    =acc[i][j][1]+sc_s[nl]+sq_s[ml+1];
      stg[(nl+8)*132+ml]  =acc[i][j][2]+sc_s[nl+8]+sq_s[ml];
      stg[(nl+8)*132+ml+1]=acc[i][j][3]+sc_s[nl+8]+sq_s[ml+1];
    }
  __syncthreads();
  {
    int nl=tid>>1, mh=(tid&1)*64;
    float mx=__int_as_float(0xff800000);
    float* Sg=g_S+(size_t)b*NM+(size_t)(n0+nl)*MM+m0+mh;
#pragma unroll
    for(int q=0;q<16;q++){
      float4 v=*(float4*)&stg[nl*132+mh+q*4];
      mx=fmaxf(mx,fmaxf(fmaxf(v.x,v.y),fmaxf(v.z,v.w)));
      *(float4*)&Sg[q*4]=v;
    }
    atomicMaxF(&g_rmax[b*NN+n0+nl],mx);
    int ml=tid>>1, nh=(tid&1)*64;
    float cx=__int_as_float(0xff800000);
#pragma unroll 8
    for(int r2=0;r2<64;r2++) cx=fmaxf(cx,stg[(nh+r2)*132+ml]);
    atomicMaxF(&g_cmax[b*MM+m0+ml],cx);
  }
}

// ---- V GEMM (round-10 structure) + folded csum + cheap split ----
__global__ void __launch_bounds__(256) k_gemmV(){
  extern __shared__ char smc[];
  __shared__ float cmx[128], csp[128][2], cin[128];
  uint32_t sb=smem_u32(smc);
  const uint32_t oAh=0u,oAl=18432u,oBh=36864u,oBl=55296u,oSs=73728u;
  float* Sst=(float*)(smc+oSs);
  int b=blockIdx.y, m0=blockIdx.x*128, tid=threadIdx.x;
  if(tid<128) cmx[tid]=g_cmax[b*MM+m0+tid];
  __syncthreads();
  int wid=tid>>5, lane=tid&31, wn=wid>>2, wm=wid&3;
  int me=tid>>1, nhb=tid&1, nh=nhb*32;
  float cme=cmx[me], csum=0.f;
  float acc[4][4][4]={};
  for(int c=0;c<32;c++){
    int n0c=c*64;
    __syncthreads();
    {
      int d=tid>>1, sg=(tid&1)*4;
      const uint4* ph=(const uint4*)&g_Cs[0][b][d][n0c];
      const uint4* pl=(const uint4*)&g_Cs[1][b][d][n0c];
#pragma unroll
      for(int j=0;j<4;j++){
        uint32_t off=(uint32_t)(d*72+(sg+j)*8)*2;
        *(uint4*)(smc+oAh+off)=ph[sg+j];
        *(uint4*)(smc+oAl+off)=pl[sg+j];
      }
      int n=tid>>2, q=tid&3;
      const float4* sr=(const float4*)(g_S+(size_t)b*NM+(size_t)(n0c+n)*MM+m0);
#pragma unroll
      for(int j=0;j<8;j++) *(float4*)&Sst[n*132+(q*8+j)*4]=sr[q*8+j];
    }
    __syncthreads();
#pragma unroll
    for(int np=0;np<16;np++){
      int n=nh+np*2;
      float e0=__expf(Sst[n*132+me]-cme);
      float e1=__expf(Sst[(n+1)*132+me]-cme);
      csum+=e0+e1;
      uint32_t hp,lp; splitpack_t(e0,e1,hp,lp);
      uint32_t off=(uint32_t)(me*72+n)*2;
      *(uint32_t*)(smc+oBh+off)=hp;
      *(uint32_t*)(smc+oBl+off)=lp;
    }
    __syncthreads();
    mma_block(acc, sb+oAh+(uint32_t)(wn*64*72)*2, sb+oAl+(uint32_t)(wn*64*72)*2,
                   sb+oBh+(uint32_t)(wm*32*72)*2, sb+oBl+(uint32_t)(wm*32*72)*2,
              72, 64, lane);
  }
  csp[me][nhb]=csum;
  __syncthreads();
  if(tid<128) cin[tid]=1.0f/(csp[tid][0]+csp[tid][1]);
  __syncthreads();
  float* stg=(float*)smc;
  int gr=lane>>2, tg=lane&3;
#pragma unroll
  for(int i=0;i<4;i++)
#pragma unroll
    for(int j=0;j<4;j++){
      int dl2=wn*64+i*16+gr, ml=wm*32+j*8+tg*2;
      stg[dl2*132+ml]      =acc[i][j][0]*cin[ml];
      stg[dl2*132+ml+1]    =acc[i][j][1]*cin[ml+1];
      stg[(dl2+8)*132+ml]  =acc[i][j][2]*cin[ml];
      stg[(dl2+8)*132+ml+1]=acc[i][j][3]*cin[ml+1];
    }
  __syncthreads();
  {
    int d=tid>>1, mhs=(tid&1)*64;
    __nv_bfloat16* vh=&g_Vs[0][b][d][m0+mhs];
    __nv_bfloat16* vl=&g_Vs[1][b][d][m0+mhs];
#pragma unroll
    for(int q=0;q<8;q++){
      __align__(16) __nv_bfloat16 hh[8],ll[8];
#pragma unroll
      for(int e=0;e<8;e++){
        float f=stg[d*132+mhs+q*8+e];
        hh[e]=__float2bfloat16(f);
        ll[e]=__float2bfloat16(f-__bfloat162float(hh[e]));
      }
      *(uint4*)&vh[q*8]=*(uint4*)hh;
      *(uint4*)&vl[q*8]=*(uint4*)ll;
    }
  }
}

// ---- A/Bt GEMM (round-10 half structure) + folded rsum + cheap split ----
__global__ void __launch_bounds__(256) k_gemmABt(const float* __restrict__ C_,
                                                 float* __restrict__ out){
  extern __shared__ char smc[];
  __shared__ float rmx[128], rsp[128][2], rin[128];
  uint32_t sb=smem_u32(smc);
  const uint32_t oPh=0u,oPl=18432u,oEh=36864u,oEl=55296u;
  int b=blockIdx.z, half=blockIdx.y, n0=blockIdx.x*128, tid=threadIdx.x;
  if(tid<128) rmx[tid]=g_rmax[b*NN+n0+tid];
  __syncthreads();
  const __nv_bfloat16* Pg0 = half? &g_Vs[0][b][0][0] : &g_Qs[0][b][0][0];
  const __nv_bfloat16* Pg1 = half? &g_Vs[1][b][0][0] : &g_Qs[1][b][0][0];
  int wid=tid>>5, lane=tid&31, wn=wid>>2, wm=wid&3;
  int ne=tid>>1, mh=(tid&1)*32;
  float rme=rmx[ne], rsum=0.f;
  float acc[4][4][4]={};
  for(int c=0;c<32;c++){
    int m0c=c*64;
    __syncthreads();
    {
      int d=tid>>1, sg=(tid&1)*4;
      const uint4* ph=(const uint4*)(Pg0+(size_t)d*MM+m0c);
      const uint4* pl=(const uint4*)(Pg1+(size_t)d*MM+m0c);
#pragma unroll
      for(int j=0;j<4;j++){
        uint32_t off=(uint32_t)(d*72+(sg+j)*8)*2;
        *(uint4*)(smc+oPh+off)=ph[sg+j];
        *(uint4*)(smc+oPl+off)=pl[sg+j];
      }
    }
    {
      const float4* sr=(const float4*)(g_S+(size_t)b*NM+(size_t)(n0+ne)*MM+m0c+mh);
#pragma unroll
      for(int j=0;j<8;j++){
        float4 v=sr[j];
        float e0=__expf(v.x-rme), e1=__expf(v.y-rme);
        float e2=__expf(v.z-rme), e3=__expf(v.w-rme);
        rsum+=(e0+e1)+(e2+e3);
        uint32_t h0,l0,h1,l1;
        splitpack_t(e0,e1,h0,l0); splitpack_t(e2,e3,h1,l1);
        uint32_t off=(uint32_t)(ne*72+mh+j*4)*2;
        *(uint2*)(smc+oEh+off)=make_uint2(h0,h1);
        *(uint2*)(smc+oEl+off)=make_uint2(l0,l1);
      }
    }
    __syncthreads();
    mma_block(acc, sb+oPh+(uint32_t)(wn*64*72)*2, sb+oPl+(uint32_t)(wn*64*72)*2,
                   sb+oEh+(uint32_t)(wm*32*72)*2, sb+oEl+(uint32_t)(wm*32*72)*2,
              72, 64, lane);
  }
  rsp[ne][tid&1]=rsum;
  __syncthreads();
  if(tid<128) rin[tid]=1.0f/(rsp[tid][0]+rsp[tid][1]);
  __syncthreads();
  float* stg=(float*)smc;
  int gr=lane>>2, tg=lane&3;
#pragma unroll
  for(int i=0;i<4;i++)
#pragma unroll
    for(int j=0;j<4;j++){
      int gl=wn*64+i*16+gr, nl=wm*32+j*8+tg*2;
      stg[gl*132+nl]      =acc[i][j][0]*rin[nl];
      stg[gl*132+nl+1]    =acc[i][j][1]*rin[nl+1];
      stg[(gl+8)*132+nl]  =acc[i][j][2]*rin[nl];
      stg[(gl+8)*132+nl+1]=acc[i][j][3]*rin[nl+1];
    }
  __syncthreads();
  {
    int nq=tid&31, dg=tid>>5;
#pragma unroll
    for(int dd=0;dd<16;dd++){
      int d=dg*16+dd;
      float4 v=*(float4*)&stg[d*132+nq*4];
      float4 c4=*(const float4*)&C_[((size_t)b*DD+d)*NN+n0+nq*4];
      unsigned ng=n0+nq*4;
      if(half==0){
        unsigned i0=(unsigned)(b*512+d)*2048u+ng;
        float4 o;
        o.x=dropf(c4.x,i0);   o.y=dropf(c4.y,i0+1);
        o.z=dropf(c4.z,i0+2); o.w=dropf(c4.w,i0+3);
        *(float4*)&out[(size_t)(b*512+d)*2048+ng]=o;
        unsigned i1=i0+128u*2048u;
        o.x=dropf(v.x,i1);   o.y=dropf(v.y,i1+1);
        o.z=dropf(v.z,i1+2); o.w=dropf(v.w,i1+3);
        *(float4*)&out[(size_t)(b*512+128+d)*2048+ng]=o;
        unsigned i2=i0+256u*2048u;
        o.x=dropf(c4.x*v.x,i2);   o.y=dropf(c4.y*v.y,i2+1);
        o.z=dropf(c4.z*v.z,i2+2); o.w=dropf(c4.w*v.w,i2+3);
        *(float4*)&out[(size_t)(b*512+256+d)*2048+ng]=o;
      } else {
        unsigned i3=(unsigned)(b*512+384+d)*2048u+ng;
        float4 o;
        o.x=dropf(c4.x*v.x,i3);   o.y=dropf(c4.y*v.y,i3+1);
        o.z=dropf(c4.z*v.z,i3+2); o.w=dropf(c4.w*v.w,i3+3);
        *(float4*)&out[(size_t)(b*512+384+d)*2048+ng]=o;
      }
    }
  }
}

extern "C" void kernel_launch(void* const* d_in, const int* in_sizes, int n_in,
                              void* d_out, int out_size){
  const float* C_=(const float*)d_in[0];
  const float* Q_=(const float*)d_in[1];
  const float* W_=(const float*)d_in[2];
  float* out=(float*)d_out;
  cudaFuncSetAttribute(k_gemmS,  cudaFuncAttributeMaxDynamicSharedMemorySize, 139264);
  cudaFuncSetAttribute(k_gemmV,  cudaFuncAttributeMaxDynamicSharedMemorySize, 107520);
  cudaFuncSetAttribute(k_gemmABt,cudaFuncAttributeMaxDynamicSharedMemorySize, 73728);
  k_init <<<(BB*NN+255)/256,256>>>();
  k_sqsc <<<dim3(MM/256,BB),256>>>(Q_,C_,W_);
  k_split<<<(unsigned)((size_t)2*BB*DD*NN/4/256),256>>>(C_,Q_);
  k_tr   <<<dim3(NN/32,DD/32,BB*2),256>>>(C_,Q_,W_);
  k_gemmS<<<dim3(MM/128,NN/128,BB),256,139264>>>();
  k_gemmV<<<dim3(MM/128,BB),256,107520>>>();
  k_gemmABt<<<dim3(NN/128,2,BB),256,73728>>>(C_,out);
}